// round 16
// baseline (speedup 1.0000x reference)
#include <cuda_runtime.h>
#include <cuda_bf16.h>
#include <cstdint>
#include <math.h>

// ---------------------------------------------------------------------------
// Problem constants
// ---------------------------------------------------------------------------
#define B_SZ   4
#define T_SZ   2048
#define DIM    2048
#define NH     16
#define NKV    4
#define HD     128
#define MTOT   (B_SZ * T_SZ)      // 8192

// ---------------------------------------------------------------------------
// Device scratch — hi/lo bf16 planes
// ---------------------------------------------------------------------------
__device__ __align__(16) __nv_bfloat16 g_hh [(size_t)MTOT * DIM];
__device__ __align__(16) __nv_bfloat16 g_hl [(size_t)MTOT * DIM];
__device__ __align__(16) __nv_bfloat16 g_wqh[(size_t)3072 * DIM];
__device__ __align__(16) __nv_bfloat16 g_wql[(size_t)3072 * DIM];
__device__ __align__(16) __nv_bfloat16 g_woh[(size_t)2048 * DIM];
__device__ __align__(16) __nv_bfloat16 g_wol[(size_t)2048 * DIM];
__device__ __align__(16) __nv_bfloat16 g_aoh[(size_t)MTOT * DIM];
__device__ __align__(16) __nv_bfloat16 g_aol[(size_t)MTOT * DIM];

__device__ __align__(16) __nv_bfloat16 g_qh[(size_t)B_SZ * NH  * T_SZ * HD];
__device__ __align__(16) __nv_bfloat16 g_ql[(size_t)B_SZ * NH  * T_SZ * HD];
__device__ __align__(16) __nv_bfloat16 g_kh[(size_t)B_SZ * NKV * T_SZ * HD];
__device__ __align__(16) __nv_bfloat16 g_kl[(size_t)B_SZ * NKV * T_SZ * HD];
__device__ __align__(16) __nv_bfloat16 g_vh[(size_t)B_SZ * NKV * T_SZ * HD];
__device__ __align__(16) __nv_bfloat16 g_vl[(size_t)B_SZ * NKV * T_SZ * HD];

// ---------------------------------------------------------------------------
// Helpers (compute_80-level PTX only)
// ---------------------------------------------------------------------------
__device__ __forceinline__ uint32_t smem_u32(const void* p) {
    uint32_t a;
    asm("{ .reg .u64 t; cvta.to.shared.u64 t, %1; cvt.u32.u64 %0, t; }" : "=r"(a) : "l"(p));
    return a;
}
#define CP16(dst, src) asm volatile("cp.async.cg.shared.global [%0], [%1], 16;" :: "r"(dst), "l"(src))
#define CP_COMMIT()    asm volatile("cp.async.commit_group;" ::: "memory")
#define CP_WAIT2()     asm volatile("cp.async.wait_group 2;" ::: "memory")
#define CP_WAIT1()     asm volatile("cp.async.wait_group 1;" ::: "memory")
#define CP_WAIT0()     asm volatile("cp.async.wait_group 0;" ::: "memory")

#define LDMX4(r0, r1, r2, r3, addr)                                              \
    asm volatile("ldmatrix.sync.aligned.m8n8.x4.shared.b16 {%0,%1,%2,%3}, [%4];" \
                 : "=r"(r0), "=r"(r1), "=r"(r2), "=r"(r3) : "r"(addr))

#define LDMX4T(r0, r1, r2, r3, addr)                                                   \
    asm volatile("ldmatrix.sync.aligned.m8n8.x4.trans.shared.b16 {%0,%1,%2,%3}, [%4];" \
                 : "=r"(r0), "=r"(r1), "=r"(r2), "=r"(r3) : "r"(addr))

#define MMA16816(c, a, b)                                                        \
    asm volatile("mma.sync.aligned.m16n8k16.row.col.f32.bf16.bf16.f32 "          \
                 "{%0,%1,%2,%3}, {%4,%5,%6,%7}, {%8,%9}, {%0,%1,%2,%3};"         \
                 : "+f"((c)[0]), "+f"((c)[1]), "+f"((c)[2]), "+f"((c)[3])        \
                 : "r"((a)[0]), "r"((a)[1]), "r"((a)[2]), "r"((a)[3]),           \
                   "r"((b)[0]), "r"((b)[1]))

__device__ __forceinline__ uint32_t pack_bf16x2(float lo, float hi) {
    __nv_bfloat162 v = __floats2bfloat162_rn(lo, hi);
    return *(uint32_t*)&v;
}

// ---------------------------------------------------------------------------
// fp32 -> (hi, lo) bf16 planes: hidden + all four weights in ONE launch.
// ---------------------------------------------------------------------------
#define HID_ELEMS ((size_t)MTOT * DIM)
__global__ void split_all(const float* __restrict__ hid,
                          const float* __restrict__ wq, const float* __restrict__ wk,
                          const float* __restrict__ wv, const float* __restrict__ wo,
                          __nv_bfloat16* __restrict__ hh_, __nv_bfloat16* __restrict__ hl_,
                          __nv_bfloat16* __restrict__ qh_, __nv_bfloat16* __restrict__ ql_,
                          __nv_bfloat16* __restrict__ oh_, __nv_bfloat16* __restrict__ ol_)
{
    size_t i = ((size_t)blockIdx.x * blockDim.x + threadIdx.x) * 4;
    const float* src;
    __nv_bfloat16 *dh, *dl;
    size_t off;
    if (i < HID_ELEMS) {
        src = hid + i; dh = hh_; dl = hl_; off = i;
    } else {
        size_t j = i - HID_ELEMS;
        size_t row = j >> 11;
        if (row < 2048)      { src = wq + j;                          dh = qh_; dl = ql_; off = j; }
        else if (row < 2560) { src = wk + (j - ((size_t)2048 << 11)); dh = qh_; dl = ql_; off = j; }
        else if (row < 3072) { src = wv + (j - ((size_t)2560 << 11)); dh = qh_; dl = ql_; off = j; }
        else                 { src = wo + (j - ((size_t)3072 << 11)); dh = oh_; dl = ol_;
                               off = j - ((size_t)3072 << 11); }
    }
    float4 v = *(const float4*)src;
    float xs[4] = {v.x, v.y, v.z, v.w};
    __nv_bfloat16 h[4], l[4];
#pragma unroll
    for (int j = 0; j < 4; j++) {
        h[j] = __float2bfloat16_rn(xs[j]);
        l[j] = __float2bfloat16_rn(xs[j] - __bfloat162float(h[j]));
    }
    *(__nv_bfloat162*)(dh + off)     = __nv_bfloat162(h[0], h[1]);
    *(__nv_bfloat162*)(dh + off + 2) = __nv_bfloat162(h[2], h[3]);
    *(__nv_bfloat162*)(dl + off)     = __nv_bfloat162(l[0], l[1]);
    *(__nv_bfloat162*)(dl + off + 2) = __nv_bfloat162(l[2], l[3]);
}

// ---------------------------------------------------------------------------
// 2-plane split-precision NT GEMM (unchanged — measured tensor 79.8%)
// ---------------------------------------------------------------------------
#define BK2    32
#define KIT2   (DIM / BK2)               // 64
#define ROW2   64
#define TILE2  (128 * ROW2)              // 8192
#define STG2   (4 * TILE2)               // 32768
#define NS2    3
#define GEMM_SMEM (NS2 * STG2)           // 98304
#define CS_PITCH 132

#define SWZ(r, j) ((r) * ROW2 + (((j) ^ (((r) >> 1) & 3)) << 4))

__device__ __forceinline__ void load_stage2(
    uint32_t st, const char* Ah, const char* Al,
    const char* Bh, const char* Bl, int it, int tid)
{
    const size_t ld = (size_t)DIM * 2;
    const size_t k0 = (size_t)it * (BK2 * 2);
    const char* base[4] = {Ah + k0, Al + k0, Bh + k0, Bl + k0};
#pragma unroll
    for (int x = 0; x < 8; x++) {
        int idx  = tid + x * 256;
        int tile = idx >> 9;
        int rem  = idx & 511;
        int r    = rem >> 2;
        int j    = rem & 3;
        CP16(st + tile * TILE2 + SWZ(r, j), base[tile] + (size_t)r * ld + j * 16);
    }
    CP_COMMIT();
}

__global__ __launch_bounds__(256, 2) void gemm2p(
    const __nv_bfloat16* __restrict__ Agh, const __nv_bfloat16* __restrict__ Agl,
    const __nv_bfloat16* __restrict__ Bgh, const __nv_bfloat16* __restrict__ Bgl,
    float* __restrict__ C0, int mode, int ldc,
    const float* __restrict__ cosb, const float* __restrict__ sinb,
    __nv_bfloat16* __restrict__ qh, __nv_bfloat16* __restrict__ ql,
    __nv_bfloat16* __restrict__ kh, __nv_bfloat16* __restrict__ kl,
    __nv_bfloat16* __restrict__ vh, __nv_bfloat16* __restrict__ vl)
{
    extern __shared__ char smraw[];
    const uint32_t sm0 = smem_u32(smraw);

    const int tid  = threadIdx.x;
    const int wid  = tid >> 5;
    const int lane = tid & 31;
    const int wm   = wid >> 2;
    const int wn   = wid & 3;
    const int bn   = blockIdx.x * 128;
    const int bm   = blockIdx.y * 128;

    const char* Ah = (const char*)(Agh + (size_t)bm * DIM);
    const char* Al = (const char*)(Agl + (size_t)bm * DIM);
    const char* Bh = (const char*)(Bgh + (size_t)bn * DIM);
    const char* Bl = (const char*)(Bgl + (size_t)bn * DIM);

    float c[4][4][4];
#pragma unroll
    for (int i = 0; i < 4; i++)
#pragma unroll
        for (int j = 0; j < 4; j++)
#pragma unroll
            for (int e = 0; e < 4; e++) c[i][j][e] = 0.0f;

    load_stage2(sm0,        Ah, Al, Bh, Bl, 0, tid);
    load_stage2(sm0 + STG2, Ah, Al, Bh, Bl, 1, tid);

    const int a_row  = wm * 64 + (lane & 15);
    const int a_chk  = lane >> 4;
    const int a_xor  = (a_row >> 1) & 3;
    const int b_row  = wn * 32 + ((lane >> 4) << 3) + (lane & 7);
    const int b_chk  = (lane >> 3) & 1;
    const int b_xor  = (b_row >> 1) & 3;

    int slot = 0;
    for (int it = 0; it < KIT2; it++) {
        CP_WAIT1();
        __syncthreads();

        const uint32_t s   = sm0 + slot * STG2;
        const uint32_t sAh = s;
        const uint32_t sAl = s + TILE2;
        const uint32_t sBh = s + 2 * TILE2;
        const uint32_t sBl = s + 3 * TILE2;

#pragma unroll
        for (int kk = 0; kk < 2; kk++) {
            const int ajc = ((a_chk + kk * 2) ^ a_xor) << 4;
            const int bjc = ((b_chk + kk * 2) ^ b_xor) << 4;
            uint32_t ah[4][4], al[4][4], bh[4][2], bl[4][2];
#pragma unroll
            for (int mf = 0; mf < 4; mf++) {
                uint32_t off = (a_row + mf * 16) * ROW2 + ajc;
                LDMX4(ah[mf][0], ah[mf][1], ah[mf][2], ah[mf][3], sAh + off);
                LDMX4(al[mf][0], al[mf][1], al[mf][2], al[mf][3], sAl + off);
            }
#pragma unroll
            for (int p = 0; p < 2; p++) {
                uint32_t off = (b_row + p * 16) * ROW2 + bjc;
                uint32_t r0, r1, r2, r3;
                LDMX4(r0, r1, r2, r3, sBh + off);
                bh[2 * p][0] = r0;     bh[2 * p][1] = r1;
                bh[2 * p + 1][0] = r2; bh[2 * p + 1][1] = r3;
                LDMX4(r0, r1, r2, r3, sBl + off);
                bl[2 * p][0] = r0;     bl[2 * p][1] = r1;
                bl[2 * p + 1][0] = r2; bl[2 * p + 1][1] = r3;
            }
#pragma unroll
            for (int mf = 0; mf < 4; mf++)
#pragma unroll
                for (int nf = 0; nf < 4; nf++)
                    MMA16816(c[mf][nf], ah[mf], bh[nf]);
#pragma unroll
            for (int mf = 0; mf < 4; mf++)
#pragma unroll
                for (int nf = 0; nf < 4; nf++)
                    MMA16816(c[mf][nf], ah[mf], bl[nf]);
#pragma unroll
            for (int mf = 0; mf < 4; mf++)
#pragma unroll
                for (int nf = 0; nf < 4; nf++)
                    MMA16816(c[mf][nf], al[mf], bh[nf]);
        }

        if (it + 2 < KIT2) {
            int ns = slot + 2; if (ns >= NS2) ns -= NS2;
            load_stage2(sm0 + ns * STG2, Ah, Al, Bh, Bl, it + 2, tid);
        } else {
            CP_COMMIT();
        }
        slot++; if (slot == NS2) slot = 0;
    }

    if (mode == 0) {
        const int mrow = bm + wm * 64 + (lane >> 2);
        const int ncol = bn + wn * 32 + (lane & 3) * 2;
#pragma unroll
        for (int mf = 0; mf < 4; mf++) {
#pragma unroll
            for (int half = 0; half < 2; half++) {
                const int m = mrow + mf * 16 + half * 8;
                float* pbase = C0 + (size_t)m * ldc;
#pragma unroll
                for (int nf = 0; nf < 4; nf++) {
                    float2 v = make_float2(c[mf][nf][half * 2], c[mf][nf][half * 2 + 1]);
                    *(float2*)(pbase + ncol + nf * 8) = v;
                }
            }
        }
        return;
    }

    // ---- mode 1: fused RoPE + hi/lo split epilogue via smem ----
    CP_WAIT0();
    __syncthreads();
    float* Cs = (float*)smraw;

    const int mloc = wm * 64 + (lane >> 2);
    const int nloc = wn * 32 + (lane & 3) * 2;
#pragma unroll
    for (int mf = 0; mf < 4; mf++) {
#pragma unroll
        for (int half = 0; half < 2; half++) {
            int r = mloc + mf * 16 + half * 8;
#pragma unroll
            for (int nf = 0; nf < 4; nf++) {
                float2 v = make_float2(c[mf][nf][half * 2], c[mf][nf][half * 2 + 1]);
                *(float2*)(Cs + r * CS_PITCH + nloc + nf * 8) = v;
            }
        }
    }
    __syncthreads();

    const int b  = bm >> 11;
    const int t0 = bm & (T_SZ - 1);
    int kind, hh;
    if (bn < 2048)      { kind = 0; hh = bn >> 7; }
    else if (bn < 2560) { kind = 1; hh = (bn - 2048) >> 7; }
    else                { kind = 2; hh = (bn - 2560) >> 7; }
    const float scale = (kind == 0) ? 0.088388347648318447f * 1.4426950408889634f
                                    : 1.0f;

    __nv_bfloat16* oh = (kind == 0) ? qh : (kind == 1) ? kh : vh;
    __nv_bfloat16* ol = (kind == 0) ? ql : (kind == 1) ? kl : vl;
    const int nheads  = (kind == 0) ? NH : NKV;

    for (int rr = 0; rr < 16; rr++) {
        int r = wid * 16 + rr;
        int t = t0 + r;
        const float* cp = cosb + ((size_t)b * T_SZ + t) * HD;
        const float* sp = sinb + ((size_t)b * T_SZ + t) * HD;
        __nv_bfloat16* obase = oh + (((size_t)(b * nheads + hh) * T_SZ + t) * HD);
        __nv_bfloat16* lbase = ol + (((size_t)(b * nheads + hh) * T_SZ + t) * HD);
#pragma unroll
        for (int p = 0; p < 2; p++) {
            int d  = lane + p * 32;
            int dd = d + 64;
            float x1 = Cs[r * CS_PITCH + d];
            float x2 = Cs[r * CS_PITCH + dd];
            float o1, o2;
            if (kind == 2) { o1 = x1; o2 = x2; }
            else {
                o1 = (x1 * cp[d]  - x2 * sp[d])  * scale;
                o2 = (x2 * cp[dd] + x1 * sp[dd]) * scale;
            }
            __nv_bfloat16 h1 = __float2bfloat16_rn(o1);
            __nv_bfloat16 h2 = __float2bfloat16_rn(o2);
            obase[d]  = h1;
            obase[dd] = h2;
            lbase[d]  = __float2bfloat16_rn(o1 - __bfloat162float(h1));
            lbase[dd] = __float2bfloat16_rn(o2 - __bfloat162float(h2));
        }
    }
}

// ---------------------------------------------------------------------------
// Flash attention R16: S-ahead software pipeline.
// 256 thr, 128-row Q tile; 32-row KV tiles, 3 stages. Each iteration issues
// all S(i+1) MMAs FIRST (fire-and-forget into c2), then runs softmax(i) on
// the ALU/MUFU pipes while the tensor pipe drains S(i+1), then PV(i).
// ---------------------------------------------------------------------------
#define AP     264
#define APB    (AP * 2)                  // 528
#define QPLANE (128 * APB)               // 67584
#define KVR    32
#define STAGE  (2 * KVR * APB)           // 33792 (K 32 rows + V 32 rows)
#define NST    3
#define ATT_SMEM (QPLANE + NST * STAGE)  // 168960

__global__ __launch_bounds__(256, 1) void attn_mma(
    const __nv_bfloat16* __restrict__ Qh, const __nv_bfloat16* __restrict__ Ql,
    const __nv_bfloat16* __restrict__ Kh, const __nv_bfloat16* __restrict__ Kl,
    const __nv_bfloat16* __restrict__ Vh, const __nv_bfloat16* __restrict__ Vl,
    __nv_bfloat16* __restrict__ Aoh, __nv_bfloat16* __restrict__ Aol)
{
    extern __shared__ char smraw[];
    const uint32_t Qs  = smem_u32(smraw);
    const uint32_t KV0 = Qs + QPLANE;

    const int tid  = threadIdx.x;
    const int wid  = tid >> 5;
    const int lane = tid & 31;
    const int qt   = 15 - blockIdx.x;    // heavy q-tiles first
    const int h    = blockIdx.y;
    const int b    = blockIdx.z;
    const int hk   = h >> 2;

    const char* Qhb = (const char*)(Qh + (((size_t)(b * NH + h) * T_SZ) + qt * 128) * HD);
    const char* Qlb = (const char*)(Ql + (((size_t)(b * NH + h) * T_SZ) + qt * 128) * HD);
    const char* Khb = (const char*)(Kh + ((size_t)(b * NKV + hk) * T_SZ) * HD);
    const char* Klb = (const char*)(Kl + ((size_t)(b * NKV + hk) * T_SZ) * HD);
    const char* Vhb = (const char*)(Vh + ((size_t)(b * NKV + hk) * T_SZ) * HD);
    const char* Vlb = (const char*)(Vl + ((size_t)(b * NKV + hk) * T_SZ) * HD);

    // ---- Q tile (128 rows, hi|lo), group 0 ----
#pragma unroll
    for (int x = 0; x < 16; x++) {
        int idx = tid + x * 256;
        int r = idx >> 5, sub = idx & 31;
        int pl = sub >> 4, cc = sub & 15;
        const char* src = (pl ? Qlb : Qhb) + (size_t)r * 256 + cc * 16;
        CP16(Qs + r * APB + pl * 256 + cc * 16, src);
    }
    CP_COMMIT();

    const int n_tiles = 4 * (qt + 1);        // 32-row kv tiles, min 4

    auto load_kv = [&](int tt, int st) {     // one commit group
        const size_t koff = (size_t)tt * KVR * 256;
        const uint32_t kb = KV0 + st * STAGE;
        const uint32_t vb = kb + KVR * APB;
#pragma unroll
        for (int x = 0; x < 4; x++) {        // K: 1024 chunks
            int idx = tid + x * 256;
            int r = idx >> 5, sub = idx & 31;
            int pl = sub >> 4, cc = sub & 15;
            CP16(kb + r * APB + pl * 256 + cc * 16,
                 (pl ? Klb : Khb) + koff + (size_t)r * 256 + cc * 16);
        }
#pragma unroll
        for (int x = 0; x < 4; x++) {        // V
            int idx = tid + x * 256;
            int r = idx >> 5, sub = idx & 31;
            int pl = sub >> 4, cc = sub & 15;
            CP16(vb + r * APB + pl * 256 + cc * 16,
                 (pl ? Vlb : Vhb) + koff + (size_t)r * 256 + cc * 16);
        }
        CP_COMMIT();
    };

    load_kv(0, 0);
    load_kv(1, 1);
    load_kv(2, 2);

    float m_i[2], l_i[2], O[16][4];
#pragma unroll
    for (int rh = 0; rh < 2; rh++) { m_i[rh] = -1e30f; l_i[rh] = 0.0f; }
#pragma unroll
    for (int nf = 0; nf < 16; nf++)
#pragma unroll
        for (int e = 0; e < 4; e++) O[nf][e] = 0.0f;

    const int arow = (wid * 16 + (lane & 15)) * APB + (((lane >> 4) << 3) << 1);
    const int brow = ((lane & 15)) * APB + (((lane >> 4) << 3) << 1);
    const int rbase = wid * 16 + (lane >> 2);
    const int cbase = (lane & 3) * 2;

    // S of one 32-row kv tile into cc (Qh*Kh + Ql*Kh + Qh*Kl)
    auto sgemm = [&](float (&cc)[4][4], uint32_t Ks) {
#pragma unroll
        for (int nf = 0; nf < 4; nf++)
#pragma unroll
            for (int e = 0; e < 4; e++) cc[nf][e] = 0.0f;
#pragma unroll
        for (int s = 0; s < 8; s++) {
            uint32_t ah[4], al[4], kh[2][4];
            LDMX4(ah[0], ah[1], ah[2], ah[3], Qs + arow +       s * 32);
            LDMX4(al[0], al[1], al[2], al[3], Qs + arow + 256 + s * 32);
#pragma unroll
            for (int f = 0; f < 2; f++)
                LDMX4(kh[f][0], kh[f][1], kh[f][2], kh[f][3],
                      Ks + f * 16 * APB + brow + s * 32);
#pragma unroll
            for (int f = 0; f < 2; f++) {        // Qh * Kh
                uint32_t be[2] = {kh[f][0], kh[f][2]}, bo[2] = {kh[f][1], kh[f][3]};
                MMA16816(cc[2 * f],     ah, be);
                MMA16816(cc[2 * f + 1], ah, bo);
            }
#pragma unroll
            for (int f = 0; f < 2; f++) {        // Ql * Kh
                uint32_t be[2] = {kh[f][0], kh[f][2]}, bo[2] = {kh[f][1], kh[f][3]};
                MMA16816(cc[2 * f],     al, be);
                MMA16816(cc[2 * f + 1], al, bo);
            }
#pragma unroll
            for (int f = 0; f < 2; f++) {        // Qh * Kl
                uint32_t r0, r1, r2, r3;
                LDMX4(r0, r1, r2, r3, Ks + f * 16 * APB + brow + 256 + s * 32);
                uint32_t be[2] = {r0, r2}, bo[2] = {r1, r3};
                MMA16816(cc[2 * f],     ah, be);
                MMA16816(cc[2 * f + 1], ah, bo);
            }
        }
    };

    float c[4][4], c2[4][4];

    // prologue: wait Q + kv0 (leave kv1, kv2 pending), compute S(0)
    CP_WAIT2();
    __syncthreads();
    sgemm(c, KV0);

    int st = 0;
    for (int i = 0; i < n_tiles; i++) {
        const uint32_t Ks = KV0 + st * STAGE;
        const uint32_t Vs = Ks + KVR * APB;
        const int stn = (st + 1 == NST) ? 0 : st + 1;
        const bool has_next = (i + 1 < n_tiles);

        if (has_next) {
            CP_WAIT1();                      // kv(i+1) landed
            __syncthreads();                 // visible to all warps
            // ---- issue S(i+1) MMAs first (fire-and-forget into c2) ----
            sgemm(c2, KV0 + stn * STAGE);
        } else {
            __syncthreads();
        }

        // ---- mask + softmax on tile i (ALU/MUFU overlap with S(i+1)) ----
        if (i >= 4 * qt) {
            const int col0 = i * KVR;
            const int row0 = qt * 128;
#pragma unroll
            for (int nf = 0; nf < 4; nf++) {
#pragma unroll
                for (int e = 0; e < 4; e++) {
                    int col = col0 + nf * 8 + cbase + (e & 1);
                    int row = row0 + rbase + (e >> 1) * 8;
                    if (col > row) c[nf][e] = -1e30f;
                }
            }
        }

        uint32_t Ph[8], Pl[8];
#pragma unroll
        for (int rh = 0; rh < 2; rh++) {
            float rm = -1e30f;
#pragma unroll
            for (int nf = 0; nf < 4; nf++)
                rm = fmaxf(rm, fmaxf(c[nf][rh * 2], c[nf][rh * 2 + 1]));
            rm = fmaxf(rm, __shfl_xor_sync(0xffffffffu, rm, 1));
            rm = fmaxf(rm, __shfl_xor_sync(0xffffffffu, rm, 2));
            float mn    = fmaxf(m_i[rh], rm);
            float alpha = exp2f(m_i[rh] - mn);
            m_i[rh] = mn;
            float rs = 0.0f;
#pragma unroll
            for (int nf = 0; nf < 4; nf++) {
                float p0 = exp2f(c[nf][rh * 2]     - mn);
                float p1 = exp2f(c[nf][rh * 2 + 1] - mn);
                rs += p0 + p1;
                __nv_bfloat16 h0 = __float2bfloat16_rn(p0);
                __nv_bfloat16 h1 = __float2bfloat16_rn(p1);
                Ph[nf * 2 + rh] = pack_bf16x2(__bfloat162float(h0), __bfloat162float(h1));
                Pl[nf * 2 + rh] = pack_bf16x2(p0 - __bfloat162float(h0),
                                              p1 - __bfloat162float(h1));
            }
            rs += __shfl_xor_sync(0xffffffffu, rs, 1);
            rs += __shfl_xor_sync(0xffffffffu, rs, 2);
            l_i[rh] = l_i[rh] * alpha + rs;
#pragma unroll
            for (int nf = 0; nf < 16; nf++) {
                O[nf][rh * 2]     *= alpha;
                O[nf][rh * 2 + 1] *= alpha;
            }
        }

        // ---- PV(i): Ph*Vh, Pl*Vh (Vh held), Ph*Vl ----
#pragma unroll
        for (int s = 0; s < 2; s++) {
            uint32_t aph[4] = {Ph[(2 * s) * 2 + 0], Ph[(2 * s) * 2 + 1],
                               Ph[(2 * s + 1) * 2 + 0], Ph[(2 * s + 1) * 2 + 1]};
            uint32_t apl[4] = {Pl[(2 * s) * 2 + 0], Pl[(2 * s) * 2 + 1],
                               Pl[(2 * s + 1) * 2 + 0], Pl[(2 * s + 1) * 2 + 1]};
            uint32_t vh[8][4];
#pragma unroll
            for (int f = 0; f < 8; f++)
                LDMX4T(vh[f][0], vh[f][1], vh[f][2], vh[f][3],
                       Vs + (s * 16 + (lane & 15)) * APB
                          + ((f * 16 + ((lane >> 4) << 3)) << 1));
#pragma unroll
            for (int f = 0; f < 8; f++) {
                uint32_t be[2] = {vh[f][0], vh[f][1]}, bo[2] = {vh[f][2], vh[f][3]};
                MMA16816(O[2 * f],     aph, be);
                MMA16816(O[2 * f + 1], aph, bo);
            }
#pragma unroll
            for (int f = 0; f < 8; f++) {
                uint32_t be[2] = {vh[f][0], vh[f][1]}, bo[2] = {vh[f][2], vh[f][3]};
                MMA16816(O[2 * f],     apl, be);
                MMA16816(O[2 * f + 1], apl, bo);
            }
#pragma unroll
            for (int f = 0; f < 8; f++) {
                uint32_t m0, m1, m2, m3;
                LDMX4T(m0, m1, m2, m3,
                       Vs + (s * 16 + (lane & 15)) * APB + 256
                          + ((f * 16 + ((lane >> 4) << 3)) << 1));
                uint32_t be[2] = {m0, m1}, bo[2] = {m2, m3};
                MMA16816(O[2 * f],     aph, be);
                MMA16816(O[2 * f + 1], aph, bo);
            }
        }

        __syncthreads();                     // all warps done with stage st
        if (i + 3 < n_tiles) load_kv(i + 3, st);
        else CP_COMMIT();                    // keep group-count invariant

        if (has_next) {
#pragma unroll
            for (int nf = 0; nf < 4; nf++)
#pragma unroll
                for (int e = 0; e < 4; e++) c[nf][e] = c2[nf][e];
        }
        st = stn;
    }

    // ---- epilogue: normalize, split hi/lo, write 2 planes ----
#pragma unroll
    for (int rh = 0; rh < 2; rh++) {
        float inv = 1.0f / l_i[rh];
        int t = qt * 128 + rbase + rh * 8;
        size_t gm = (size_t)b * T_SZ + t;
        __nv_bfloat16* oph = Aoh + gm * DIM + h * HD;
        __nv_bfloat16* opl = Aol + gm * DIM + h * HD;
#pragma unroll
        for (int nf = 0; nf < 16; nf++) {
            float o0 = O[nf][rh * 2]     * inv;
            float o1 = O[nf][rh * 2 + 1] * inv;
            __nv_bfloat16 h0 = __float2bfloat16_rn(o0);
            __nv_bfloat16 h1 = __float2bfloat16_rn(o1);
            uint32_t hi = pack_bf16x2(__bfloat162float(h0), __bfloat162float(h1));
            uint32_t lo = pack_bf16x2(o0 - __bfloat162float(h0), o1 - __bfloat162float(h1));
            int k = nf * 8 + cbase;
            *(uint32_t*)(oph + k) = hi;
            *(uint32_t*)(opl + k) = lo;
        }
    }
}

// ---------------------------------------------------------------------------
// kernel_launch
// ---------------------------------------------------------------------------
extern "C" void kernel_launch(void* const* d_in, const int* in_sizes, int n_in,
                              void* d_out, int out_size)
{
    (void)in_sizes; (void)n_in; (void)out_size;
    const float* hidden = (const float*)d_in[0];
    const float* cosb   = (const float*)d_in[1];
    const float* sinb   = (const float*)d_in[2];
    const float* wq     = (const float*)d_in[3];
    const float* wk     = (const float*)d_in[4];
    const float* wv     = (const float*)d_in[5];
    const float* wo     = (const float*)d_in[6];
    float* out = (float*)d_out;

    __nv_bfloat16 *ghh, *ghl, *gwqh, *gwql, *gwoh, *gwol, *gaoh, *gaol;
    __nv_bfloat16 *gqh, *gql, *gkh, *gkl, *gvh, *gvl;
    cudaGetSymbolAddress((void**)&ghh,  g_hh);
    cudaGetSymbolAddress((void**)&ghl,  g_hl);
    cudaGetSymbolAddress((void**)&gwqh, g_wqh);
    cudaGetSymbolAddress((void**)&gwql, g_wql);
    cudaGetSymbolAddress((void**)&gwoh, g_woh);
    cudaGetSymbolAddress((void**)&gwol, g_wol);
    cudaGetSymbolAddress((void**)&gaoh, g_aoh);
    cudaGetSymbolAddress((void**)&gaol, g_aol);
    cudaGetSymbolAddress((void**)&gqh,  g_qh);
    cudaGetSymbolAddress((void**)&gql,  g_ql);
    cudaGetSymbolAddress((void**)&gkh,  g_kh);
    cudaGetSymbolAddress((void**)&gkl,  g_kl);
    cudaGetSymbolAddress((void**)&gvh,  g_vh);
    cudaGetSymbolAddress((void**)&gvl,  g_vl);

    cudaFuncSetAttribute(gemm2p,   cudaFuncAttributeMaxDynamicSharedMemorySize, GEMM_SMEM);
    cudaFuncSetAttribute(attn_mma, cudaFuncAttributeMaxDynamicSharedMemorySize, ATT_SMEM);

    // --- hi/lo plane conversions: hidden + all weights in ONE launch ---
    split_all<<<(unsigned)((HID_ELEMS + (size_t)5120 * DIM) / 4 / 256), 256>>>(
        hidden, wq, wk, wv, wo, ghh, ghl, gwqh, gwql, gwoh, gwol);

    // --- fused QKV projection + RoPE + hi/lo split epilogue ---
    gemm2p<<<dim3(3072 / 128, MTOT / 128), 256, GEMM_SMEM>>>(
        ghh, ghl, gwqh, gwql, nullptr, 1, 0, cosb, sinb,
        gqh, gql, gkh, gkl, gvh, gvl);

    // --- Flash attention (S-ahead pipeline, 32-row KV tiles, 3 stages) ---
    attn_mma<<<dim3(T_SZ / 128, NH, B_SZ), 256, ATT_SMEM>>>(
        gqh, gql, gkh, gkl, gvh, gvl, gaoh, gaol);

    // --- wo projection ---
    gemm2p<<<dim3(DIM / 128, MTOT / 128), 256, GEMM_SMEM>>>(
        gaoh, gaol, gwoh, gwol, out, 0, DIM, nullptr, nullptr,
        nullptr, nullptr, nullptr, nullptr, nullptr, nullptr);
}

// round 17
// speedup vs baseline: 1.2531x; 1.2531x over previous
#include <cuda_runtime.h>
#include <cuda_bf16.h>
#include <cuda_fp16.h>
#include <cstdint>
#include <math.h>

// ---------------------------------------------------------------------------
// Problem constants
// ---------------------------------------------------------------------------
#define B_SZ   4
#define T_SZ   2048
#define DIM    2048
#define NH     16
#define NKV    4
#define HD     128
#define MTOT   (B_SZ * T_SZ)      // 8192

// ---------------------------------------------------------------------------
// Device scratch
//  GEMM operands: fp16 (A-side hi/lo exact split, B-side hi only)
//  Attention operands: bf16 hi/lo (3-pass split, proven numerics)
// ---------------------------------------------------------------------------
__device__ __align__(16) __half g_hh [(size_t)MTOT * DIM];   // hidden hi
__device__ __align__(16) __half g_hl [(size_t)MTOT * DIM];   // hidden lo
__device__ __align__(16) __half g_wqh[(size_t)3072 * DIM];   // wq|wk|wv hi
__device__ __align__(16) __half g_woh[(size_t)2048 * DIM];   // wo hi
__device__ __align__(16) __half g_aoh[(size_t)MTOT * DIM];   // attn out hi
__device__ __align__(16) __half g_aol[(size_t)MTOT * DIM];   // attn out lo

__device__ __align__(16) __nv_bfloat16 g_qh[(size_t)B_SZ * NH  * T_SZ * HD];
__device__ __align__(16) __nv_bfloat16 g_ql[(size_t)B_SZ * NH  * T_SZ * HD];
__device__ __align__(16) __nv_bfloat16 g_kh[(size_t)B_SZ * NKV * T_SZ * HD];
__device__ __align__(16) __nv_bfloat16 g_kl[(size_t)B_SZ * NKV * T_SZ * HD];
__device__ __align__(16) __nv_bfloat16 g_vh[(size_t)B_SZ * NKV * T_SZ * HD];
__device__ __align__(16) __nv_bfloat16 g_vl[(size_t)B_SZ * NKV * T_SZ * HD];

// ---------------------------------------------------------------------------
// Helpers (compute_80-level PTX only)
// ---------------------------------------------------------------------------
__device__ __forceinline__ uint32_t smem_u32(const void* p) {
    uint32_t a;
    asm("{ .reg .u64 t; cvta.to.shared.u64 t, %1; cvt.u32.u64 %0, t; }" : "=r"(a) : "l"(p));
    return a;
}
#define CP16(dst, src) asm volatile("cp.async.cg.shared.global [%0], [%1], 16;" :: "r"(dst), "l"(src))
#define CP_COMMIT()    asm volatile("cp.async.commit_group;" ::: "memory")
#define CP_WAIT1()     asm volatile("cp.async.wait_group 1;" ::: "memory")
#define CP_WAIT0()     asm volatile("cp.async.wait_group 0;" ::: "memory")

#define LDMX4(r0, r1, r2, r3, addr)                                              \
    asm volatile("ldmatrix.sync.aligned.m8n8.x4.shared.b16 {%0,%1,%2,%3}, [%4];" \
                 : "=r"(r0), "=r"(r1), "=r"(r2), "=r"(r3) : "r"(addr))

#define LDMX4T(r0, r1, r2, r3, addr)                                                   \
    asm volatile("ldmatrix.sync.aligned.m8n8.x4.trans.shared.b16 {%0,%1,%2,%3}, [%4];" \
                 : "=r"(r0), "=r"(r1), "=r"(r2), "=r"(r3) : "r"(addr))

// bf16 MMA (attention)
#define MMA16816(c, a, b)                                                        \
    asm volatile("mma.sync.aligned.m16n8k16.row.col.f32.bf16.bf16.f32 "          \
                 "{%0,%1,%2,%3}, {%4,%5,%6,%7}, {%8,%9}, {%0,%1,%2,%3};"         \
                 : "+f"((c)[0]), "+f"((c)[1]), "+f"((c)[2]), "+f"((c)[3])        \
                 : "r"((a)[0]), "r"((a)[1]), "r"((a)[2]), "r"((a)[3]),           \
                   "r"((b)[0]), "r"((b)[1]))

// fp16 MMA (projection GEMMs)
#define MMAH16816(c, a, b)                                                       \
    asm volatile("mma.sync.aligned.m16n8k16.row.col.f32.f16.f16.f32 "            \
                 "{%0,%1,%2,%3}, {%4,%5,%6,%7}, {%8,%9}, {%0,%1,%2,%3};"         \
                 : "+f"((c)[0]), "+f"((c)[1]), "+f"((c)[2]), "+f"((c)[3])        \
                 : "r"((a)[0]), "r"((a)[1]), "r"((a)[2]), "r"((a)[3]),           \
                   "r"((b)[0]), "r"((b)[1]))

__device__ __forceinline__ uint32_t pack_bf16x2(float lo, float hi) {
    __nv_bfloat162 v = __floats2bfloat162_rn(lo, hi);
    return *(uint32_t*)&v;
}
__device__ __forceinline__ uint32_t pack_h16x2(float lo, float hi) {
    __half2 v = __floats2half2_rn(lo, hi);
    return *(uint32_t*)&v;
}

// ---------------------------------------------------------------------------
// fp32 -> fp16 planes: hidden (hi+lo) and all four weights (hi only), ONE launch
// ---------------------------------------------------------------------------
#define HID_ELEMS ((size_t)MTOT * DIM)
__global__ void split_all(const float* __restrict__ hid,
                          const float* __restrict__ wq, const float* __restrict__ wk,
                          const float* __restrict__ wv, const float* __restrict__ wo,
                          __half* __restrict__ hh_, __half* __restrict__ hl_,
                          __half* __restrict__ qh_, __half* __restrict__ oh_)
{
    size_t i = ((size_t)blockIdx.x * blockDim.x + threadIdx.x) * 4;
    if (i < HID_ELEMS) {
        float4 v = *(const float4*)(hid + i);
        float xs[4] = {v.x, v.y, v.z, v.w};
        __half h[4], l[4];
#pragma unroll
        for (int j = 0; j < 4; j++) {
            h[j] = __float2half_rn(xs[j]);
            l[j] = __float2half_rn(xs[j] - __half2float(h[j]));
        }
        *(__half2*)(hh_ + i)     = __halves2half2(h[0], h[1]);
        *(__half2*)(hh_ + i + 2) = __halves2half2(h[2], h[3]);
        *(__half2*)(hl_ + i)     = __halves2half2(l[0], l[1]);
        *(__half2*)(hl_ + i + 2) = __halves2half2(l[2], l[3]);
    } else {
        size_t j = i - HID_ELEMS;
        size_t row = j >> 11;
        const float* src;
        __half* dh;
        size_t off;
        if (row < 2048)      { src = wq + j;                          dh = qh_; off = j; }
        else if (row < 2560) { src = wk + (j - ((size_t)2048 << 11)); dh = qh_; off = j; }
        else if (row < 3072) { src = wv + (j - ((size_t)2560 << 11)); dh = qh_; off = j; }
        else                 { src = wo + (j - ((size_t)3072 << 11)); dh = oh_;
                               off = j - ((size_t)3072 << 11); }
        float4 v = *(const float4*)src;
        *(__half2*)(dh + off)     = __floats2half2_rn(v.x, v.y);
        *(__half2*)(dh + off + 2) = __floats2half2_rn(v.z, v.w);
    }
}

// ---------------------------------------------------------------------------
// fp16 2-pass split NT GEMM:  C = Ah*Bh^T + Al*Bh^T   (fp32 accum, K = 2048)
// Tile 128x128xBK32, 3-stage pipeline, single barrier/iter, XOR swizzle,
// 8 warps (2Mx4N, warp 64x32), occupancy 2. Stage = Ah|Al|Bh (3 tiles).
// mode 0: C fp32 [M, ldc];  mode 1: fused RoPE + bf16 hi/lo q/k/v epilogue.
// ---------------------------------------------------------------------------
#define BK2    32
#define KIT2   (DIM / BK2)               // 64
#define ROW2   64
#define TILE2  (128 * ROW2)              // 8192
#define STG2   (3 * TILE2)               // 24576 (Ah|Al|Bh)
#define NS2    3
#define GEMM_SMEM (NS2 * STG2)           // 73728
#define CS_PITCH 132

#define SWZ(r, j) ((r) * ROW2 + (((j) ^ (((r) >> 1) & 3)) << 4))

__device__ __forceinline__ void load_stage2(
    uint32_t st, const char* Ah, const char* Al, const char* Bh, int it, int tid)
{
    const size_t ld = (size_t)DIM * 2;
    const size_t k0 = (size_t)it * (BK2 * 2);
    const char* base[3] = {Ah + k0, Al + k0, Bh + k0};
#pragma unroll
    for (int x = 0; x < 6; x++) {            // 1536 16B chunks
        int idx  = tid + x * 256;
        int tile = idx >> 9;
        int rem  = idx & 511;
        int r    = rem >> 2;
        int j    = rem & 3;
        CP16(st + tile * TILE2 + SWZ(r, j), base[tile] + (size_t)r * ld + j * 16);
    }
    CP_COMMIT();
}

__global__ __launch_bounds__(256, 2) void gemm2p(
    const __half* __restrict__ Agh, const __half* __restrict__ Agl,
    const __half* __restrict__ Bgh,
    float* __restrict__ C0, int mode, int ldc,
    const float* __restrict__ cosb, const float* __restrict__ sinb,
    __nv_bfloat16* __restrict__ qh, __nv_bfloat16* __restrict__ ql,
    __nv_bfloat16* __restrict__ kh, __nv_bfloat16* __restrict__ kl,
    __nv_bfloat16* __restrict__ vh, __nv_bfloat16* __restrict__ vl)
{
    extern __shared__ char smraw[];
    const uint32_t sm0 = smem_u32(smraw);

    const int tid  = threadIdx.x;
    const int wid  = tid >> 5;
    const int lane = tid & 31;
    const int wm   = wid >> 2;
    const int wn   = wid & 3;
    const int bn   = blockIdx.x * 128;
    const int bm   = blockIdx.y * 128;

    const char* Ah = (const char*)(Agh + (size_t)bm * DIM);
    const char* Al = (const char*)(Agl + (size_t)bm * DIM);
    const char* Bh = (const char*)(Bgh + (size_t)bn * DIM);

    float c[4][4][4];
#pragma unroll
    for (int i = 0; i < 4; i++)
#pragma unroll
        for (int j = 0; j < 4; j++)
#pragma unroll
            for (int e = 0; e < 4; e++) c[i][j][e] = 0.0f;

    load_stage2(sm0,        Ah, Al, Bh, 0, tid);
    load_stage2(sm0 + STG2, Ah, Al, Bh, 1, tid);

    const int a_row  = wm * 64 + (lane & 15);
    const int a_chk  = lane >> 4;
    const int a_xor  = (a_row >> 1) & 3;
    const int b_row  = wn * 32 + ((lane >> 4) << 3) + (lane & 7);
    const int b_chk  = (lane >> 3) & 1;
    const int b_xor  = (b_row >> 1) & 3;

    int slot = 0;
    for (int it = 0; it < KIT2; it++) {
        CP_WAIT1();
        __syncthreads();

        const uint32_t s   = sm0 + slot * STG2;
        const uint32_t sAh = s;
        const uint32_t sAl = s + TILE2;
        const uint32_t sBh = s + 2 * TILE2;

#pragma unroll
        for (int kk = 0; kk < 2; kk++) {
            const int ajc = ((a_chk + kk * 2) ^ a_xor) << 4;
            const int bjc = ((b_chk + kk * 2) ^ b_xor) << 4;
            uint32_t ah[4][4], al[4][4], bh[4][2];
#pragma unroll
            for (int mf = 0; mf < 4; mf++) {
                uint32_t off = (a_row + mf * 16) * ROW2 + ajc;
                LDMX4(ah[mf][0], ah[mf][1], ah[mf][2], ah[mf][3], sAh + off);
                LDMX4(al[mf][0], al[mf][1], al[mf][2], al[mf][3], sAl + off);
            }
#pragma unroll
            for (int p = 0; p < 2; p++) {
                uint32_t off = (b_row + p * 16) * ROW2 + bjc;
                uint32_t r0, r1, r2, r3;
                LDMX4(r0, r1, r2, r3, sBh + off);
                bh[2 * p][0] = r0;     bh[2 * p][1] = r1;
                bh[2 * p + 1][0] = r2; bh[2 * p + 1][1] = r3;
            }
#pragma unroll
            for (int mf = 0; mf < 4; mf++)
#pragma unroll
                for (int nf = 0; nf < 4; nf++)
                    MMAH16816(c[mf][nf], ah[mf], bh[nf]);
#pragma unroll
            for (int mf = 0; mf < 4; mf++)
#pragma unroll
                for (int nf = 0; nf < 4; nf++)
                    MMAH16816(c[mf][nf], al[mf], bh[nf]);
        }

        if (it + 2 < KIT2) {
            int ns = slot + 2; if (ns >= NS2) ns -= NS2;
            load_stage2(sm0 + ns * STG2, Ah, Al, Bh, it + 2, tid);
        } else {
            CP_COMMIT();
        }
        slot++; if (slot == NS2) slot = 0;
    }

    if (mode == 0) {
        const int mrow = bm + wm * 64 + (lane >> 2);
        const int ncol = bn + wn * 32 + (lane & 3) * 2;
#pragma unroll
        for (int mf = 0; mf < 4; mf++) {
#pragma unroll
            for (int half = 0; half < 2; half++) {
                const int m = mrow + mf * 16 + half * 8;
                float* pbase = C0 + (size_t)m * ldc;
#pragma unroll
                for (int nf = 0; nf < 4; nf++) {
                    float2 v = make_float2(c[mf][nf][half * 2], c[mf][nf][half * 2 + 1]);
                    *(float2*)(pbase + ncol + nf * 8) = v;
                }
            }
        }
        return;
    }

    // ---- mode 1: fused RoPE + bf16 hi/lo split epilogue via smem ----
    CP_WAIT0();
    __syncthreads();
    float* Cs = (float*)smraw;           // 128 x 132 floats = 67584 <= 73728

    const int mloc = wm * 64 + (lane >> 2);
    const int nloc = wn * 32 + (lane & 3) * 2;
#pragma unroll
    for (int mf = 0; mf < 4; mf++) {
#pragma unroll
        for (int half = 0; half < 2; half++) {
            int r = mloc + mf * 16 + half * 8;
#pragma unroll
            for (int nf = 0; nf < 4; nf++) {
                float2 v = make_float2(c[mf][nf][half * 2], c[mf][nf][half * 2 + 1]);
                *(float2*)(Cs + r * CS_PITCH + nloc + nf * 8) = v;
            }
        }
    }
    __syncthreads();

    const int b  = bm >> 11;
    const int t0 = bm & (T_SZ - 1);
    int kind, hh;
    if (bn < 2048)      { kind = 0; hh = bn >> 7; }
    else if (bn < 2560) { kind = 1; hh = (bn - 2048) >> 7; }
    else                { kind = 2; hh = (bn - 2560) >> 7; }
    // Q scale folded with log2(e) for the exp2-domain softmax
    const float scale = (kind == 0) ? 0.088388347648318447f * 1.4426950408889634f
                                    : 1.0f;

    __nv_bfloat16* oh = (kind == 0) ? qh : (kind == 1) ? kh : vh;
    __nv_bfloat16* ol = (kind == 0) ? ql : (kind == 1) ? kl : vl;
    const int nheads  = (kind == 0) ? NH : NKV;

    for (int rr = 0; rr < 16; rr++) {
        int r = wid * 16 + rr;
        int t = t0 + r;
        const float* cp = cosb + ((size_t)b * T_SZ + t) * HD;
        const float* sp = sinb + ((size_t)b * T_SZ + t) * HD;
        __nv_bfloat16* obase = oh + (((size_t)(b * nheads + hh) * T_SZ + t) * HD);
        __nv_bfloat16* lbase = ol + (((size_t)(b * nheads + hh) * T_SZ + t) * HD);
#pragma unroll
        for (int p = 0; p < 2; p++) {
            int d  = lane + p * 32;
            int dd = d + 64;
            float x1 = Cs[r * CS_PITCH + d];
            float x2 = Cs[r * CS_PITCH + dd];
            float o1, o2;
            if (kind == 2) { o1 = x1; o2 = x2; }
            else {
                o1 = (x1 * cp[d]  - x2 * sp[d])  * scale;
                o2 = (x2 * cp[dd] + x1 * sp[dd]) * scale;
            }
            __nv_bfloat16 h1 = __float2bfloat16_rn(o1);
            __nv_bfloat16 h2 = __float2bfloat16_rn(o2);
            obase[d]  = h1;
            obase[dd] = h2;
            lbase[d]  = __float2bfloat16_rn(o1 - __bfloat162float(h1));
            lbase[dd] = __float2bfloat16_rn(o2 - __bfloat162float(h2));
        }
    }
}

// ---------------------------------------------------------------------------
// Flash attention (exact R12 core — best measured 655.7 µs).
// 256 thr, 128-row Q, 64-row KV, 2-stage, pass-major waves, exp2 softmax.
// Epilogue emits fp16 hi/lo planes for the wo GEMM.
// ---------------------------------------------------------------------------
#define AP     264
#define APB    (AP * 2)
#define QPLANE (128 * APB)
#define KVHALF (64 * APB)
#define ATT_SMEM (QPLANE + 4 * KVHALF)

__global__ __launch_bounds__(256, 1) void attn_mma(
    const __nv_bfloat16* __restrict__ Qh, const __nv_bfloat16* __restrict__ Ql,
    const __nv_bfloat16* __restrict__ Kh, const __nv_bfloat16* __restrict__ Kl,
    const __nv_bfloat16* __restrict__ Vh, const __nv_bfloat16* __restrict__ Vl,
    __half* __restrict__ Aoh, __half* __restrict__ Aol)
{
    extern __shared__ char smraw[];
    const uint32_t Qs  = smem_u32(smraw);
    const uint32_t KV0 = Qs + QPLANE;

    const int tid  = threadIdx.x;
    const int wid  = tid >> 5;
    const int lane = tid & 31;
    const int qt   = 15 - blockIdx.x;
    const int h    = blockIdx.y;
    const int b    = blockIdx.z;
    const int hk   = h >> 2;

    const char* Qhb = (const char*)(Qh + (((size_t)(b * NH + h) * T_SZ) + qt * 128) * HD);
    const char* Qlb = (const char*)(Ql + (((size_t)(b * NH + h) * T_SZ) + qt * 128) * HD);
    const char* Khb = (const char*)(Kh + ((size_t)(b * NKV + hk) * T_SZ) * HD);
    const char* Klb = (const char*)(Kl + ((size_t)(b * NKV + hk) * T_SZ) * HD);
    const char* Vhb = (const char*)(Vh + ((size_t)(b * NKV + hk) * T_SZ) * HD);
    const char* Vlb = (const char*)(Vl + ((size_t)(b * NKV + hk) * T_SZ) * HD);

#pragma unroll
    for (int x = 0; x < 16; x++) {
        int idx = tid + x * 256;
        int r = idx >> 5, sub = idx & 31;
        int pl = sub >> 4, cc = sub & 15;
        const char* src = (pl ? Qlb : Qhb) + (size_t)r * 256 + cc * 16;
        CP16(Qs + r * APB + pl * 256 + cc * 16, src);
    }
    CP_COMMIT();

    const int n_tiles = 2 * (qt + 1);

    auto load_kv = [&](int tt, int st) {
        const size_t koff = (size_t)tt * 64 * 256;
        const uint32_t kb = KV0 + st * 2 * KVHALF;
        const uint32_t vb = kb + KVHALF;
#pragma unroll
        for (int x = 0; x < 8; x++) {
            int idx = tid + x * 256;
            int r = idx >> 5, sub = idx & 31;
            int pl = sub >> 4, cc = sub & 15;
            CP16(kb + r * APB + pl * 256 + cc * 16,
                 (pl ? Klb : Khb) + koff + (size_t)r * 256 + cc * 16);
        }
#pragma unroll
        for (int x = 0; x < 8; x++) {
            int idx = tid + x * 256;
            int r = idx >> 5, sub = idx & 31;
            int pl = sub >> 4, cc = sub & 15;
            CP16(vb + r * APB + pl * 256 + cc * 16,
                 (pl ? Vlb : Vhb) + koff + (size_t)r * 256 + cc * 16);
        }
        CP_COMMIT();
    };

    load_kv(0, 0);
    load_kv(1, 1);

    float m_i[2], l_i[2], O[16][4];
#pragma unroll
    for (int rh = 0; rh < 2; rh++) { m_i[rh] = -1e30f; l_i[rh] = 0.0f; }
#pragma unroll
    for (int nf = 0; nf < 16; nf++)
#pragma unroll
        for (int e = 0; e < 4; e++) O[nf][e] = 0.0f;

    const int arow = (wid * 16 + (lane & 15)) * APB + (((lane >> 4) << 3) << 1);
    const int brow = ((lane & 15)) * APB + (((lane >> 4) << 3) << 1);
    const int rbase = wid * 16 + (lane >> 2);
    const int cbase = (lane & 3) * 2;

    for (int i = 0; i < n_tiles; i++) {
        const int st = i & 1;
        const uint32_t Ks = KV0 + st * 2 * KVHALF;
        const uint32_t Vs = Ks + KVHALF;

        CP_WAIT1();
        __syncthreads();

        // ---- S: wave1 ah*Kh, wave2 al*Kh (Kh held), wave3 ah*Kl ----
        float c[8][4];
#pragma unroll
        for (int nf = 0; nf < 8; nf++)
#pragma unroll
            for (int e = 0; e < 4; e++) c[nf][e] = 0.0f;

#pragma unroll
        for (int s = 0; s < 8; s++) {
            uint32_t ah[4], al[4], kh[4][4];
            LDMX4(ah[0], ah[1], ah[2], ah[3], Qs + arow +       s * 32);
            LDMX4(al[0], al[1], al[2], al[3], Qs + arow + 256 + s * 32);
#pragma unroll
            for (int f = 0; f < 4; f++)
                LDMX4(kh[f][0], kh[f][1], kh[f][2], kh[f][3],
                      Ks + f * 16 * APB + brow + s * 32);
#pragma unroll
            for (int f = 0; f < 4; f++) {
                uint32_t be[2] = {kh[f][0], kh[f][2]}, bo[2] = {kh[f][1], kh[f][3]};
                MMA16816(c[2 * f],     ah, be);
                MMA16816(c[2 * f + 1], ah, bo);
            }
#pragma unroll
            for (int f = 0; f < 4; f++) {
                uint32_t be[2] = {kh[f][0], kh[f][2]}, bo[2] = {kh[f][1], kh[f][3]};
                MMA16816(c[2 * f],     al, be);
                MMA16816(c[2 * f + 1], al, bo);
            }
#pragma unroll
            for (int f = 0; f < 4; f++) {
                uint32_t r0, r1, r2, r3;
                LDMX4(r0, r1, r2, r3, Ks + f * 16 * APB + brow + 256 + s * 32);
                uint32_t be[2] = {r0, r2}, bo[2] = {r1, r3};
                MMA16816(c[2 * f],     ah, be);
                MMA16816(c[2 * f + 1], ah, bo);
            }
        }

        if (i >= 2 * qt) {
            const int col0 = i * 64;
            const int row0 = qt * 128;
#pragma unroll
            for (int nf = 0; nf < 8; nf++) {
#pragma unroll
                for (int e = 0; e < 4; e++) {
                    int col = col0 + nf * 8 + cbase + (e & 1);
                    int row = row0 + rbase + (e >> 1) * 8;
                    if (col > row) c[nf][e] = -1e30f;
                }
            }
        }

        // ---- online softmax (exp2 domain) + pack P ----
        uint32_t Ph[16], Pl[16];
#pragma unroll
        for (int rh = 0; rh < 2; rh++) {
            float rm = -1e30f;
#pragma unroll
            for (int nf = 0; nf < 8; nf++)
                rm = fmaxf(rm, fmaxf(c[nf][rh * 2], c[nf][rh * 2 + 1]));
            rm = fmaxf(rm, __shfl_xor_sync(0xffffffffu, rm, 1));
            rm = fmaxf(rm, __shfl_xor_sync(0xffffffffu, rm, 2));
            float mn    = fmaxf(m_i[rh], rm);
            float alpha = exp2f(m_i[rh] - mn);
            m_i[rh] = mn;
            float rs = 0.0f;
#pragma unroll
            for (int nf = 0; nf < 8; nf++) {
                float p0 = exp2f(c[nf][rh * 2]     - mn);
                float p1 = exp2f(c[nf][rh * 2 + 1] - mn);
                rs += p0 + p1;
                __nv_bfloat16 h0 = __float2bfloat16_rn(p0);
                __nv_bfloat16 h1 = __float2bfloat16_rn(p1);
                Ph[nf * 2 + rh] = pack_bf16x2(__bfloat162float(h0), __bfloat162float(h1));
                Pl[nf * 2 + rh] = pack_bf16x2(p0 - __bfloat162float(h0),
                                              p1 - __bfloat162float(h1));
            }
            rs += __shfl_xor_sync(0xffffffffu, rs, 1);
            rs += __shfl_xor_sync(0xffffffffu, rs, 2);
            l_i[rh] = l_i[rh] * alpha + rs;
#pragma unroll
            for (int nf = 0; nf < 16; nf++) {
                O[nf][rh * 2]     *= alpha;
                O[nf][rh * 2 + 1] *= alpha;
            }
        }

        // ---- PV: wave1 Ph*Vh, wave2 Pl*Vh (Vh held), wave3 Ph*Vl ----
#pragma unroll
        for (int s = 0; s < 4; s++) {
            uint32_t aph[4] = {Ph[(2 * s) * 2 + 0], Ph[(2 * s) * 2 + 1],
                               Ph[(2 * s + 1) * 2 + 0], Ph[(2 * s + 1) * 2 + 1]};
            uint32_t apl[4] = {Pl[(2 * s) * 2 + 0], Pl[(2 * s) * 2 + 1],
                               Pl[(2 * s + 1) * 2 + 0], Pl[(2 * s + 1) * 2 + 1]};
            uint32_t vh[8][4];
#pragma unroll
            for (int f = 0; f < 8; f++)
                LDMX4T(vh[f][0], vh[f][1], vh[f][2], vh[f][3],
                       Vs + (s * 16 + (lane & 15)) * APB
                          + ((f * 16 + ((lane >> 4) << 3)) << 1));
#pragma unroll
            for (int f = 0; f < 8; f++) {
                uint32_t be[2] = {vh[f][0], vh[f][1]}, bo[2] = {vh[f][2], vh[f][3]};
                MMA16816(O[2 * f],     aph, be);
                MMA16816(O[2 * f + 1], aph, bo);
            }
#pragma unroll
            for (int f = 0; f < 8; f++) {
                uint32_t be[2] = {vh[f][0], vh[f][1]}, bo[2] = {vh[f][2], vh[f][3]};
                MMA16816(O[2 * f],     apl, be);
                MMA16816(O[2 * f + 1], apl, bo);
            }
#pragma unroll
            for (int f = 0; f < 8; f++) {
                uint32_t m0, m1, m2, m3;
                LDMX4T(m0, m1, m2, m3,
                       Vs + (s * 16 + (lane & 15)) * APB + 256
                          + ((f * 16 + ((lane >> 4) << 3)) << 1));
                uint32_t be[2] = {m0, m1}, bo[2] = {m2, m3};
                MMA16816(O[2 * f],     aph, be);
                MMA16816(O[2 * f + 1], aph, bo);
            }
        }

        __syncthreads();
        if (i + 2 < n_tiles) load_kv(i + 2, st);
        else CP_COMMIT();
    }

    // ---- epilogue: normalize, fp16 hi/lo split, write 2 planes for wo GEMM ----
#pragma unroll
    for (int rh = 0; rh < 2; rh++) {
        float inv = 1.0f / l_i[rh];
        int t = qt * 128 + rbase + rh * 8;
        size_t gm = (size_t)b * T_SZ + t;
        __half* oph = Aoh + gm * DIM + h * HD;
        __half* opl = Aol + gm * DIM + h * HD;
#pragma unroll
        for (int nf = 0; nf < 16; nf++) {
            float o0 = O[nf][rh * 2]     * inv;
            float o1 = O[nf][rh * 2 + 1] * inv;
            __half h0 = __float2half_rn(o0);
            __half h1 = __float2half_rn(o1);
            uint32_t hi = pack_h16x2(__half2float(h0), __half2float(h1));
            uint32_t lo = pack_h16x2(o0 - __half2float(h0), o1 - __half2float(h1));
            int k = nf * 8 + cbase;
            *(uint32_t*)(oph + k) = hi;
            *(uint32_t*)(opl + k) = lo;
        }
    }
}

// ---------------------------------------------------------------------------
// kernel_launch
// ---------------------------------------------------------------------------
extern "C" void kernel_launch(void* const* d_in, const int* in_sizes, int n_in,
                              void* d_out, int out_size)
{
    (void)in_sizes; (void)n_in; (void)out_size;
    const float* hidden = (const float*)d_in[0];
    const float* cosb   = (const float*)d_in[1];
    const float* sinb   = (const float*)d_in[2];
    const float* wq     = (const float*)d_in[3];
    const float* wk     = (const float*)d_in[4];
    const float* wv     = (const float*)d_in[5];
    const float* wo     = (const float*)d_in[6];
    float* out = (float*)d_out;

    __half *ghh, *ghl, *gwqh, *gwoh, *gaoh, *gaol;
    __nv_bfloat16 *gqh, *gql, *gkh, *gkl, *gvh, *gvl;
    cudaGetSymbolAddress((void**)&ghh,  g_hh);
    cudaGetSymbolAddress((void**)&ghl,  g_hl);
    cudaGetSymbolAddress((void**)&gwqh, g_wqh);
    cudaGetSymbolAddress((void**)&gwoh, g_woh);
    cudaGetSymbolAddress((void**)&gaoh, g_aoh);
    cudaGetSymbolAddress((void**)&gaol, g_aol);
    cudaGetSymbolAddress((void**)&gqh,  g_qh);
    cudaGetSymbolAddress((void**)&gql,  g_ql);
    cudaGetSymbolAddress((void**)&gkh,  g_kh);
    cudaGetSymbolAddress((void**)&gkl,  g_kl);
    cudaGetSymbolAddress((void**)&gvh,  g_vh);
    cudaGetSymbolAddress((void**)&gvl,  g_vl);

    cudaFuncSetAttribute(gemm2p,   cudaFuncAttributeMaxDynamicSharedMemorySize, GEMM_SMEM);
    cudaFuncSetAttribute(attn_mma, cudaFuncAttributeMaxDynamicSharedMemorySize, ATT_SMEM);

    // --- fp16 plane conversions: hidden hi/lo + weights hi, ONE launch ---
    split_all<<<(unsigned)((HID_ELEMS + (size_t)5120 * DIM) / 4 / 256), 256>>>(
        hidden, wq, wk, wv, wo, ghh, ghl, gwqh, gwoh);

    // --- fused QKV projection (fp16 2-pass) + RoPE + bf16 split epilogue ---
    gemm2p<<<dim3(3072 / 128, MTOT / 128), 256, GEMM_SMEM>>>(
        ghh, ghl, gwqh, nullptr, 1, 0, cosb, sinb,
        gqh, gql, gkh, gkl, gvh, gvl);

    // --- Flash attention (R12 core) -> fp16 hi/lo attn-out planes ---
    attn_mma<<<dim3(T_SZ / 128, NH, B_SZ), 256, ATT_SMEM>>>(
        gqh, gql, gkh, gkl, gvh, gvl, gaoh, gaol);

    // --- wo projection (fp16 2-pass) ---
    gemm2p<<<dim3(DIM / 128, MTOT / 128), 256, GEMM_SMEM>>>(
        gaoh, gaol, gwoh, out, 0, DIM, nullptr, nullptr,
        nullptr, nullptr, nullptr, nullptr, nullptr, nullptr);
}